// round 8
// baseline (speedup 1.0000x reference)
#include <cuda_runtime.h>
#include <cuda_fp16.h>
#include <cstdint>
#include <cstddef>

// Problem constants (B=8, S=2048, D=1024, F=4096, E=8, capacity_factor=1.0)
#define T_TOK   16384
#define D_DIM   1024
#define F_DIM   4096
#define E_NUM   8
#define CAP     2048
#define CHUNK   256
#define NCHUNK  (T_TOK / CHUNK)

#define BM 128
#define BN 128
#define NTHREADS 128
#define ROWB 64              // 32 fp16 per k-tile row
#define STAGE_B 16384        // A 8KB + B 8KB per stage (3 stages = 48KB)

// ---------------- device scratch (~288 MB) ----------------
__device__ int   g_eidx[T_TOK];
__device__ float g_gate[T_TOK];
__device__ int   g_keep[T_TOK];
__device__ int   g_counts[NCHUNK][E_NUM];     // zero-init; scan re-zeroes after read
__device__ int   g_base[NCHUNK][E_NUM];
__device__ int   g_tok_of_slot[E_NUM * CAP];
__device__ float g_slot_gate[E_NUM * CAP];

__device__ __half g_x16[(size_t)T_TOK * D_DIM];               //  32 MB  A1 fp16
__device__ __half g_wt[(size_t)E_NUM * F_DIM * D_DIM];        //  64 MB  W1t
__device__ __half g_wt2[(size_t)E_NUM * D_DIM * F_DIM];       //  64 MB  W2t
__device__ __half g_h16[(size_t)E_NUM * CAP * F_DIM];         // 128 MB  H fp16
__device__ uint4  g_zrow[512];                                //   8 KB zero row

// ---------------- PTX helpers ----------------
__device__ __forceinline__ uint32_t smem_u32(const void* p) {
    uint32_t a;
    asm("{ .reg .u64 t; cvta.to.shared.u64 t, %1; cvt.u32.u64 %0, t; }" : "=r"(a) : "l"(p));
    return a;
}
__device__ __forceinline__ void sts128(uint32_t a, uint4 v) {
    asm volatile("st.shared.v4.b32 [%0], {%1,%2,%3,%4};"
                 :: "r"(a), "r"(v.x), "r"(v.y), "r"(v.z), "r"(v.w) : "memory");
}
__device__ __forceinline__ void ldsm4(uint32_t& r0, uint32_t& r1, uint32_t& r2, uint32_t& r3, uint32_t a) {
    asm volatile("ldmatrix.sync.aligned.m8n8.x4.shared.b16 {%0,%1,%2,%3}, [%4];"
                 : "=r"(r0), "=r"(r1), "=r"(r2), "=r"(r3) : "r"(a));
}
__device__ __forceinline__ void mma16816(float* c, const uint32_t* a, const uint32_t* b) {
    asm volatile("mma.sync.aligned.m16n8k16.row.col.f32.f16.f16.f32 "
                 "{%0,%1,%2,%3}, {%4,%5,%6,%7}, {%8,%9}, {%0,%1,%2,%3};"
                 : "+f"(c[0]), "+f"(c[1]), "+f"(c[2]), "+f"(c[3])
                 : "r"(a[0]), "r"(a[1]), "r"(a[2]), "r"(a[3]), "r"(b[0]), "r"(b[1]));
}

// ---------------- router (+ fused x->fp16 + fused chunk histogram) --------
__global__ void router_kernel(const float* __restrict__ x,
                              const float* __restrict__ Wr) {
    __shared__ float sWr[D_DIM * E_NUM];
    for (int i = threadIdx.x; i < D_DIM * E_NUM; i += blockDim.x)
        sWr[i] = Wr[i];
    __syncthreads();

    const int warp = threadIdx.x >> 5;
    const int lane = threadIdx.x & 31;
    const int tok  = blockIdx.x * (blockDim.x >> 5) + warp;
    const float* xr = x + (size_t)tok * D_DIM;
    __half* xo = g_x16 + (size_t)tok * D_DIM;

    float acc[E_NUM];
#pragma unroll
    for (int e = 0; e < E_NUM; e++) acc[e] = 0.f;
    for (int d = lane; d < D_DIM; d += 32) {
        float xv = xr[d];
        xo[d] = __float2half_rn(xv);               // fused conversion
        const float* w = &sWr[d * E_NUM];
#pragma unroll
        for (int e = 0; e < E_NUM; e++) acc[e] += xv * w[e];
    }
#pragma unroll
    for (int e = 0; e < E_NUM; e++) {
#pragma unroll
        for (int o = 16; o > 0; o >>= 1)
            acc[e] += __shfl_xor_sync(0xffffffffu, acc[e], o);
    }
    if (lane == 0) {
        int best = 0; float bm = acc[0];
#pragma unroll
        for (int e = 1; e < E_NUM; e++)
            if (acc[e] > bm) { bm = acc[e]; best = e; }
        float s = 0.f;
#pragma unroll
        for (int e = 0; e < E_NUM; e++) s += __expf(acc[e] - bm);
        g_eidx[tok] = best;
        g_gate[tok] = 1.0f / s;
        atomicAdd(&g_counts[tok >> 8][best], 1);   // fused chunk histogram
    }
}

// ---------------- W tile transpose+convert (256-thread body, for W1) -------
__device__ __forceinline__ void convert_w_tile(const float* __restrict__ W,
                                               __half* __restrict__ dstbuf,
                                               int K, int N, int e, int k0, int n0,
                                               int tx, int ty) {
    __shared__ float s[32][33];
    const float* src = W + (size_t)e * K * N;
    __half* d = dstbuf + (size_t)e * N * K;
#pragma unroll
    for (int i = 0; i < 4; i++) {
        int kl = ty + i * 8;
        s[kl][tx] = src[(size_t)(k0 + kl) * N + n0 + tx];
    }
    __syncthreads();
#pragma unroll
    for (int i = 0; i < 4; i++) {
        int nl = ty + i * 8;
        d[(size_t)(n0 + nl) * K + k0 + tx] = __float2half_rn(s[tx][nl]);
    }
}

// ---------------- fused: reset (b<64) | scan (b==64) | convert W1 (b>=65) --
__global__ void fused_setup_kernel(const float* __restrict__ W1) {
    int b = blockIdx.x;
    int tid = threadIdx.x;
    if (b < 64) {
        int i = b * 256 + tid;
        g_tok_of_slot[i] = -1;
        g_slot_gate[i]   = 0.f;
        g_keep[i]        = 0;
        if (i < 512) g_zrow[i] = make_uint4(0u, 0u, 0u, 0u);
    } else if (b == 64) {
        // warp w = expert w; lanes cover 64 chunks (2 each); re-zero counts after read
        int w = tid >> 5, lane = tid & 31;
        int c0 = g_counts[2 * lane][w];
        int c1 = g_counts[2 * lane + 1][w];
        g_counts[2 * lane][w] = 0;
        g_counts[2 * lane + 1][w] = 0;
        int s = c0 + c1;
        int pre = s;
#pragma unroll
        for (int o = 1; o < 32; o <<= 1) {
            int t = __shfl_up_sync(0xffffffffu, pre, o);
            if (lane >= o) pre += t;
        }
        int excl = pre - s;
        g_base[2 * lane][w]     = excl;
        g_base[2 * lane + 1][w] = excl + c0;
    } else {
        // convert W1 [e][D][F] -> g_wt [e][F][D]
        int idx = b - 65;
        int kt = idx & 31;
        int nt = (idx >> 5) & 127;
        int e  = idx >> 12;
        convert_w_tile(W1, g_wt, D_DIM, F_DIM, e, kt * 32, nt * 32, tid & 31, tid >> 5);
    }
}

__global__ void assign_kernel() {
    __shared__ int se[CHUNK];
    int tok = blockIdx.x * CHUNK + threadIdx.x;
    int e = g_eidx[tok];
    se[threadIdx.x] = e;
    __syncthreads();
    int local = 0;
    for (int j = 0; j < threadIdx.x; j++) local += (se[j] == e);
    int rank = g_base[blockIdx.x][e] + local;
    if (rank < CAP) {
        int slot = e * CAP + rank;
        g_tok_of_slot[slot] = tok;
        g_slot_gate[slot]   = g_gate[tok];
        g_keep[tok]         = 1;
    }
}

// ---------------- HMMA GEMM: 128x128 tile, BK=32, 3-stage smem pipeline ----
// smem swizzle: 16B granule g of row r stored at granule (g ^ ((r>>1)&3))
// PHASE 1: H = relu( gather(x16) @ W1t^T )  (K=1024)  + extra blocks convert W2
// PHASE 2: out[tok] = gate * ( H @ W2t^T )  (K=4096)  + extra blocks zero dropped rows
template <int PHASE>
__global__ void __launch_bounds__(NTHREADS, 2)
moe_mma_gemm(float* __restrict__ out, const float* __restrict__ w2src) {
    constexpr int KA   = (PHASE == 1) ? D_DIM : F_DIM;
    constexpr int NC   = KA / 32;
    constexpr int NT   = (PHASE == 1) ? F_DIM : D_DIM;
    constexpr int NBLK = NT / BN;               // fat GEMM blocks in x

    __shared__ uint4 dsm[3072];                 // 48 KB: 3 stages x (A 8KB + B 8KB)

    const int tid = threadIdx.x;

    // ---------- extra-block dispatch ----------
    if (blockIdx.x >= NBLK) {
        if (PHASE == 1) {
            // convert W2 [e][F][D] -> g_wt2 [e][D][F] (128-thread tile, smem aliased on dsm)
            int idx = (blockIdx.x - NBLK) + 256 * (blockIdx.y + 16 * blockIdx.z);
            int kt = idx & 127, nt = (idx >> 7) & 31, e2 = idx >> 12;
            int k0 = kt * 32, n0 = nt * 32;
            int tx = tid & 31, ty = tid >> 5;   // (32, 4)
            float (*s)[33] = (float(*)[33])dsm;
            const float* src = w2src + (size_t)e2 * F_DIM * D_DIM;
            __half* d = g_wt2 + (size_t)e2 * D_DIM * F_DIM;
#pragma unroll
            for (int i = 0; i < 8; i++) {
                int kl = ty + i * 4;
                s[kl][tx] = src[(size_t)(k0 + kl) * D_DIM + n0 + tx];
            }
            __syncthreads();
#pragma unroll
            for (int i = 0; i < 8; i++) {
                int nl = ty + i * 4;
                d[(size_t)(n0 + nl) * F_DIM + k0 + tx] = __float2half_rn(s[tx][nl]);
            }
        } else {
            // zero dropped-token rows (only one (y,z) lane does it)
            if (blockIdx.y == 0 && blockIdx.z == 0) {
                int chunk = blockIdx.x - NBLK;
                for (int t = 0; t < CHUNK; t++) {
                    int tok = chunk * CHUNK + t;
                    if (!g_keep[tok]) {
                        float4 z = make_float4(0.f, 0.f, 0.f, 0.f);
                        float4* row = (float4*)(out + (size_t)tok * D_DIM);
#pragma unroll
                        for (int j = 0; j < 2; j++)
                            row[tid + j * 128] = z;
                    }
                }
            }
        }
        return;
    }

    const uint32_t sbase = smem_u32(dsm);
    const int e = blockIdx.z, m0 = blockIdx.y * BM, n0 = blockIdx.x * BN;

    // ---- load mapping
    const int rbase = tid >> 2;
    const int cix   = tid & 3;
    const uint32_t dst0 = (uint32_t)rbase * ROWB + (uint32_t)((cix ^ ((rbase >> 1) & 3)) << 4);

    const char* pA[4];
    const char* pB[4];
    uint32_t    mskA = 0;
#pragma unroll
    for (int i = 0; i < 4; i++) {
        int row = rbase + i * 32;
        if (PHASE == 1) {
            int tok = g_tok_of_slot[e * CAP + m0 + row];
            if (tok >= 0) { pA[i] = (const char*)(g_x16 + (size_t)tok * D_DIM) + cix * 16; mskA |= (1u << i); }
            else          { pA[i] = (const char*)g_zrow; }
        } else {
            pA[i] = (const char*)(g_h16 + (size_t)(e * CAP + m0 + row) * F_DIM) + cix * 16;
            mskA |= (1u << i);
        }
        const __half* wb = (PHASE == 1) ? g_wt : g_wt2;
        pB[i] = (const char*)(wb + ((size_t)e * NT + n0 + row) * KA) + cix * 16;
    }

    uint4 rA[4], rB[4];
    auto ldg_tile = [&](int c) {
        uint32_t koff = (uint32_t)c * ROWB;
#pragma unroll
        for (int i = 0; i < 4; i++) {
            rA[i] = *(const uint4*)(pA[i] + (((mskA >> i) & 1) ? koff : 0u));
            rB[i] = *(const uint4*)(pB[i] + koff);
        }
    };
    auto sts_tile = [&](int buf) {
        uint32_t aS = sbase + (uint32_t)buf * STAGE_B;
        uint32_t bS = aS + 8192;
#pragma unroll
        for (int i = 0; i < 4; i++) {
            sts128(aS + dst0 + i * 2048, rA[i]);
            sts128(bS + dst0 + i * 2048, rB[i]);
        }
    };

    // ---- compute mapping: 4 warps 2x2, warp tile 64x64
    const int w = tid >> 5, l = tid & 31;
    const int warp_m = (w & 1) * 64, warp_n = (w >> 1) * 64;
    const int a_ml = warp_m + (l & 15);
    const int a_ks = (l >> 4);
    const int b_nl = warp_n + (l & 7) + ((l & 16) >> 1);
    const int b_ks = (l >> 3) & 1;
    const int fa = (a_ml >> 1) & 3, fb = (b_nl >> 1) & 3;

    float acc[4][8][4];
#pragma unroll
    for (int i = 0; i < 4; i++)
#pragma unroll
        for (int j = 0; j < 8; j++)
#pragma unroll
            for (int q = 0; q < 4; q++) acc[i][j][q] = 0.f;

    ldg_tile(0);
    sts_tile(0);
    ldg_tile(1);

    int bufc = 0, bufs = 1;
#pragma unroll 2
    for (int c = 0; c < NC; c++) {
        if (c + 1 < NC) sts_tile(bufs);
        if (c + 2 < NC) ldg_tile(c + 2);
        __syncthreads();

        uint32_t aS = sbase + (uint32_t)bufc * STAGE_B;
        uint32_t bS = aS + 8192;
#pragma unroll
        for (int ks = 0; ks < 2; ks++) {
            uint32_t af[4][4], bf[4][4];
#pragma unroll
            for (int mf = 0; mf < 4; mf++) {
                uint32_t addr = aS + (uint32_t)(a_ml + mf * 16) * ROWB
                              + (uint32_t)(((ks * 2 + a_ks) ^ fa) << 4);
                ldsm4(af[mf][0], af[mf][1], af[mf][2], af[mf][3], addr);
            }
#pragma unroll
            for (int g = 0; g < 4; g++) {
                uint32_t addr = bS + (uint32_t)(b_nl + g * 16) * ROWB
                              + (uint32_t)(((ks * 2 + b_ks) ^ fb) << 4);
                ldsm4(bf[g][0], bf[g][1], bf[g][2], bf[g][3], addr);
            }
#pragma unroll
            for (int mf = 0; mf < 4; mf++)
#pragma unroll
                for (int nf = 0; nf < 8; nf++)
                    mma16816(acc[mf][nf], af[mf], &bf[nf >> 1][(nf & 1) * 2]);
        }
        bufc = (bufc == 2) ? 0 : bufc + 1;
        bufs = (bufs == 2) ? 0 : bufs + 1;
    }

    // ---- epilogue ----
    const int gid = l >> 2, tg = l & 3;
    if (PHASE == 1) {
#pragma unroll
        for (int mf = 0; mf < 4; mf++) {
#pragma unroll
            for (int half = 0; half < 2; half++) {
                int row = warp_m + mf * 16 + gid + half * 8;
                int slot = e * CAP + m0 + row;
                __half* hrow = g_h16 + (size_t)slot * F_DIM;
#pragma unroll
                for (int nf = 0; nf < 8; nf++) {
                    int col = n0 + warp_n + nf * 8 + tg * 2;
                    float v0 = fmaxf(acc[mf][nf][half * 2 + 0], 0.f);
                    float v1 = fmaxf(acc[mf][nf][half * 2 + 1], 0.f);
                    *(__half2*)(hrow + col) = __halves2half2(__float2half_rn(v0), __float2half_rn(v1));
                }
            }
        }
    } else {
#pragma unroll
        for (int mf = 0; mf < 4; mf++) {
#pragma unroll
            for (int half = 0; half < 2; half++) {
                int row = warp_m + mf * 16 + gid + half * 8;
                int slot = e * CAP + m0 + row;
                int tok = g_tok_of_slot[slot];
                if (tok < 0) continue;
                float g = g_slot_gate[slot];
                float* orow = out + (size_t)tok * D_DIM;
#pragma unroll
                for (int nf = 0; nf < 8; nf++) {
                    int col = n0 + warp_n + nf * 8 + tg * 2;
                    float2 v;
                    v.x = acc[mf][nf][half * 2 + 0] * g;
                    v.y = acc[mf][nf][half * 2 + 1] * g;
                    *(float2*)(orow + col) = v;
                }
            }
        }
    }
}

// ---------------- launch ----------------
extern "C" void kernel_launch(void* const* d_in, const int* in_sizes, int n_in,
                              void* d_out, int out_size) {
    const float* x  = (const float*)d_in[0];
    const float* Wr = (const float*)d_in[1];
    const float* W1 = (const float*)d_in[2];
    const float* W2 = (const float*)d_in[3];
    float* out = (float*)d_out;

    // 0: router (+x16 conversion, +chunk histogram)
    router_kernel<<<T_TOK / 8, 256>>>(x, Wr);
    // 1: fused reset | scan | convert W1
    fused_setup_kernel<<<65 + 32 * 128 * 8, 256>>>(W1);
    // 2: slot assignment (+keep flags)
    assign_kernel<<<NCHUNK, CHUNK>>>();
    // 3: GEMM1 + overlapped W2 conversion (extra blocks)
    moe_mma_gemm<1><<<dim3(F_DIM / BN + 256, CAP / BM, E_NUM), NTHREADS>>>(nullptr, W2);
    // 4: GEMM2 + overlapped zeroing of dropped rows (extra blocks)
    moe_mma_gemm<2><<<dim3(D_DIM / BN + 64, CAP / BM, E_NUM), NTHREADS>>>(out, nullptr);
}